// round 2
// baseline (speedup 1.0000x reference)
#include <cuda_runtime.h>

// LSTM T=4096, B=2048, I=2, H=4, L=4. Gate order i,f,g,o.
// One warp per batch element. Half 0 (lanes 0-15) owns layers 0,1;
// half 1 (lanes 16-31) owns layers 2,3. Within a half, lane g = gate row g.
// Skewed wavefront: body(s) computes L0(s), L1(s-1), L2(s-2), L3(s-3).
// Cross-half handoff: h[1] broadcast lanes 0-3 -> all (width-32 shuffles).

#define TT 4096
#define BB 2048
#define LL 4

__device__ __forceinline__ float ex2f(float x) {
    float y; asm("ex2.approx.f32 %0, %1;" : "=f"(y) : "f"(x)); return y;
}
__device__ __forceinline__ float rcpf(float x) {
    float y; asm("rcp.approx.f32 %0, %1;" : "=f"(y) : "f"(x)); return y;
}

__global__ __launch_bounds__(128) void lstm_kernel(
    const float* __restrict__ x,     // (T, B, 2)
    const float* __restrict__ h0g,   // (L, B, 4)
    const float* __restrict__ c0g,   // (L, B, 4)
    const float* __restrict__ Wih0,  // (16, 2)
    const float* __restrict__ Wr,    // (3, 16, 4)  W_ih of layers 1..3
    const float* __restrict__ Whh,   // (4, 16, 4)
    const float* __restrict__ bih,   // (4, 16)
    const float* __restrict__ bhh,   // (4, 16)
    float* __restrict__ out)         // ys (T,B,4) ++ hT (L,B,4) ++ cT (L,B,4)
{
    const int lane  = threadIdx.x & 31;
    const int warp  = threadIdx.x >> 5;
    const int batch = blockIdx.x * 4 + warp;
    const int half  = lane >> 4;         // 0: layers 0,1;  1: layers 2,3
    const int g     = lane & 15;         // gate row 0..15 within layer
    const int j     = g & 3;             // hidden unit
    const int gt    = g >> 2;            // 0=i,1=f,2=g,3=o
    const int la    = half * 2;          // layer a
    const int lb    = la + 1;            // layer b

    // ---- weights in registers ----
    float win_a[4], win_b[4], wh_a[4], wh_b[4];
    if (half == 0) {
        win_a[0] = Wih0[g * 2 + 0]; win_a[1] = Wih0[g * 2 + 1];
        win_a[2] = 0.f;             win_a[3] = 0.f;
    } else {
#pragma unroll
        for (int k = 0; k < 4; k++) win_a[k] = Wr[(1 * 16 + g) * 4 + k]; // layer2 Wih
    }
    {
        const int m = half ? 2 : 0;       // layer1 -> Wr[0], layer3 -> Wr[2]
#pragma unroll
        for (int k = 0; k < 4; k++) win_b[k] = Wr[(m * 16 + g) * 4 + k];
    }
#pragma unroll
    for (int k = 0; k < 4; k++) {
        wh_a[k] = Whh[(la * 16 + g) * 4 + k];
        wh_b[k] = Whh[(lb * 16 + g) * 4 + k];
    }
    const float bz_a = bih[la * 16 + g] + bhh[la * 16 + g];
    const float bz_b = bih[lb * 16 + g] + bhh[lb * 16 + g];

    const bool  isg = (gt == 2);
    const float s1  = isg ? -2.8853900817779268f : -1.4426950408889634f;
    const float m2  = isg ? 2.0f : 1.0f;
    const float a2  = isg ? -1.0f : 0.0f;

    // ---- states ----
    float h_a[4], h_b[4], hin[4], c_a, c_b;
    {
        float4 va = *reinterpret_cast<const float4*>(h0g + (la * BB + batch) * 4);
        h_a[0] = va.x; h_a[1] = va.y; h_a[2] = va.z; h_a[3] = va.w;
        float4 vb = *reinterpret_cast<const float4*>(h0g + (lb * BB + batch) * 4);
        h_b[0] = vb.x; h_b[1] = vb.y; h_b[2] = vb.z; h_b[3] = vb.w;
    }
    c_a = c0g[(la * BB + batch) * 4 + j];
    c_b = c0g[(lb * BB + batch) * 4 + j];

    float* __restrict__ ys  = out;
    float* __restrict__ hso = out + (size_t)TT * BB * 4;
    float* __restrict__ cso = hso + (size_t)LL * BB * 4;

    const float* xb = x + batch * 2;
    float2 xa = *reinterpret_cast<const float2*>(xb);                  // x[0]
    float2 xn = *reinterpret_cast<const float2*>(xb + (size_t)BB * 2); // x[1]

    // initial hin: half0 = (x0[0], x0[1], -, -); half1 = h0 of layer 1
    {
        float t0 = __shfl_sync(0xffffffffu, h_b[0], 0, 32);
        float t1 = __shfl_sync(0xffffffffu, h_b[1], 1, 32);
        float t2 = __shfl_sync(0xffffffffu, h_b[2], 2, 32);
        float t3 = __shfl_sync(0xffffffffu, h_b[3], 3, 32);
        hin[0] = half ? t0 : xa.x;
        hin[1] = half ? t1 : xa.y;
        hin[2] = t2; hin[3] = t3;
    }

    // one layer update: activation, gate gather, cell, tanh, hidden broadcast
    auto update = [&](float z, float cc_old, float& cc_new,
                      float& h0o, float& h1o, float& h2o, float& h3o) {
        float a    = rcpf(1.0f + ex2f(z * s1));
        float gate = fmaf(a, m2, a2);
        float iv = __shfl_sync(0xffffffffu, gate, j,      16);
        float fv = __shfl_sync(0xffffffffu, gate, j + 4,  16);
        float gv = __shfl_sync(0xffffffffu, gate, j + 8,  16);
        float ov = __shfl_sync(0xffffffffu, gate, j + 12, 16);
        cc_new = fmaf(fv, cc_old, iv * gv);
        float r  = rcpf(1.0f + ex2f(cc_new * -2.8853900817779268f));
        float th = fmaf(r, 2.0f, -1.0f);
        float ho = ov * th;
        h0o = __shfl_sync(0xffffffffu, ho, 0, 16);
        h1o = __shfl_sync(0xffffffffu, ho, 1, 16);
        h2o = __shfl_sync(0xffffffffu, ho, 2, 16);
        h3o = __shfl_sync(0xffffffffu, ho, 3, 16);
    };

    auto body = [&](int s, bool masked) {
        // prefetch x two bodies ahead
        int tp = s + 2; if (tp > TT - 1) tp = TT - 1;
        float2 xf = *reinterpret_cast<const float2*>(xb + (size_t)tp * BB * 2);

        // active windows: layer l live for s in [l, l+TT-1]
        bool Aa = true, Ab = true;
        if (masked) {
            Aa = ((unsigned)(s - la) < (unsigned)TT);
            Ab = ((unsigned)(s - lb) < (unsigned)TT);
        }

        // pre-activations from OLD state
        float z_a = bz_a, z_b = bz_b;
#pragma unroll
        for (int k = 0; k < 4; k++) z_a = fmaf(win_a[k], hin[k], z_a);
#pragma unroll
        for (int k = 0; k < 4; k++) z_a = fmaf(wh_a[k], h_a[k], z_a);
#pragma unroll
        for (int k = 0; k < 4; k++) z_b = fmaf(win_b[k], h_a[k], z_b);
#pragma unroll
        for (int k = 0; k < 4; k++) z_b = fmaf(wh_b[k], h_b[k], z_b);

        // two independent layer updates
        float cna, na0, na1, na2, na3;
        update(z_a, c_a, cna, na0, na1, na2, na3);
        float cnb, nb0, nb1, nb2, nb3;
        update(z_b, c_b, cnb, nb0, nb1, nb2, nb3);

        if (Aa) {
            c_a = cna; h_a[0] = na0; h_a[1] = na1; h_a[2] = na2; h_a[3] = na3;
        }
        if (Ab) {
            c_b = cnb; h_b[0] = nb0; h_b[1] = nb1; h_b[2] = nb2; h_b[3] = nb3;
            if (half == 1 && g == 0) {   // layer 3 output row s-3
                *reinterpret_cast<float4*>(ys + ((size_t)(s - 3) * BB + batch) * 4) =
                    make_float4(h_b[0], h_b[1], h_b[2], h_b[3]);
            }
        }

        // cross-half handoff: h[1] (half0's h_b) -> hin of half1 for next body
        float t0 = __shfl_sync(0xffffffffu, h_b[0], 0, 32);
        float t1 = __shfl_sync(0xffffffffu, h_b[1], 1, 32);
        float t2 = __shfl_sync(0xffffffffu, h_b[2], 2, 32);
        float t3 = __shfl_sync(0xffffffffu, h_b[3], 3, 32);

        xa = xn; xn = xf;
        hin[0] = half ? t0 : xa.x;
        hin[1] = half ? t1 : xa.y;
        hin[2] = t2; hin[3] = t3;
    };

    body(0, true); body(1, true); body(2, true);
#pragma unroll 1
    for (int s = 3; s < TT; s++) body(s, false);
    body(TT, true); body(TT + 1, true); body(TT + 2, true);

    // ---- final hT / cT ----
    if (g == 0) {   // lanes 0 and 16
        *reinterpret_cast<float4*>(hso + (la * BB + batch) * 4) =
            make_float4(h_a[0], h_a[1], h_a[2], h_a[3]);
        *reinterpret_cast<float4*>(hso + (lb * BB + batch) * 4) =
            make_float4(h_b[0], h_b[1], h_b[2], h_b[3]);
    }
    if (gt == 0) {  // lanes 0-3 and 16-19
        cso[(la * BB + batch) * 4 + j] = c_a;
        cso[(lb * BB + batch) * 4 + j] = c_b;
    }
}

extern "C" void kernel_launch(void* const* d_in, const int* in_sizes, int n_in,
                              void* d_out, int out_size) {
    (void)in_sizes; (void)n_in; (void)out_size;
    const float* x    = (const float*)d_in[0];
    const float* h0   = (const float*)d_in[1];
    const float* c0   = (const float*)d_in[2];
    const float* Wih0 = (const float*)d_in[3];
    const float* Wr   = (const float*)d_in[4];
    const float* Whh  = (const float*)d_in[5];
    const float* bih  = (const float*)d_in[6];
    const float* bhh  = (const float*)d_in[7];
    // one warp per batch element: 2048 warps, 4 warps/block -> 512 blocks
    lstm_kernel<<<BB / 4, 128>>>(x, h0, c0, Wih0, Wr, Whh, bih, bhh, (float*)d_out);
}

// round 3
// speedup vs baseline: 1.0031x; 1.0031x over previous
#include <cuda_runtime.h>

// LSTM T=4096, B=2048, I=2, H=4, L=4. Gate order i,f,g,o.
// One warp per batch element. Half 0 (lanes 0-15) owns layers 0,1;
// half 1 (lanes 16-31) owns layers 2,3. Within a half, lane g = gate row g.
// Skewed wavefront: body(s) computes L0(s), L1(s-1), L2(s-2), L3(s-3).
// Cross-half handoff: h[1] broadcast lanes 0-3 -> all (width-32 shuffles).

#define TT 4096
#define BB 2048
#define LL 4

__device__ __forceinline__ float ex2f(float x) {
    float y; asm("ex2.approx.f32 %0, %1;" : "=f"(y) : "f"(x)); return y;
}
__device__ __forceinline__ float rcpf(float x) {
    float y; asm("rcp.approx.f32 %0, %1;" : "=f"(y) : "f"(x)); return y;
}

__global__ __launch_bounds__(128) void lstm_kernel(
    const float* __restrict__ x,     // (T, B, 2)
    const float* __restrict__ h0g,   // (L, B, 4)
    const float* __restrict__ c0g,   // (L, B, 4)
    const float* __restrict__ Wih0,  // (16, 2)
    const float* __restrict__ Wr,    // (3, 16, 4)  W_ih of layers 1..3
    const float* __restrict__ Whh,   // (4, 16, 4)
    const float* __restrict__ bih,   // (4, 16)
    const float* __restrict__ bhh,   // (4, 16)
    float* __restrict__ out)         // ys (T,B,4) ++ hT (L,B,4) ++ cT (L,B,4)
{
    const int lane  = threadIdx.x & 31;
    const int warp  = threadIdx.x >> 5;
    const int batch = blockIdx.x * 4 + warp;
    const int half  = lane >> 4;         // 0: layers 0,1;  1: layers 2,3
    const int g     = lane & 15;         // gate row 0..15 within layer
    const int j     = g & 3;             // hidden unit
    const int gt    = g >> 2;            // 0=i,1=f,2=g,3=o
    const int la    = half * 2;          // layer a
    const int lb    = la + 1;            // layer b

    // ---- weights in registers ----
    float win_a[4], win_b[4], wh_a[4], wh_b[4];
    if (half == 0) {
        win_a[0] = Wih0[g * 2 + 0]; win_a[1] = Wih0[g * 2 + 1];
        win_a[2] = 0.f;             win_a[3] = 0.f;
    } else {
#pragma unroll
        for (int k = 0; k < 4; k++) win_a[k] = Wr[(1 * 16 + g) * 4 + k]; // layer2 Wih
    }
    {
        const int m = half ? 2 : 0;       // layer1 -> Wr[0], layer3 -> Wr[2]
#pragma unroll
        for (int k = 0; k < 4; k++) win_b[k] = Wr[(m * 16 + g) * 4 + k];
    }
#pragma unroll
    for (int k = 0; k < 4; k++) {
        wh_a[k] = Whh[(la * 16 + g) * 4 + k];
        wh_b[k] = Whh[(lb * 16 + g) * 4 + k];
    }
    const float bz_a = bih[la * 16 + g] + bhh[la * 16 + g];
    const float bz_b = bih[lb * 16 + g] + bhh[lb * 16 + g];

    const bool  isg = (gt == 2);
    const float s1  = isg ? -2.8853900817779268f : -1.4426950408889634f;
    const float m2  = isg ? 2.0f : 1.0f;
    const float a2  = isg ? -1.0f : 0.0f;

    // ---- states ----
    float h_a[4], h_b[4], hin[4], c_a, c_b;
    {
        float4 va = *reinterpret_cast<const float4*>(h0g + (la * BB + batch) * 4);
        h_a[0] = va.x; h_a[1] = va.y; h_a[2] = va.z; h_a[3] = va.w;
        float4 vb = *reinterpret_cast<const float4*>(h0g + (lb * BB + batch) * 4);
        h_b[0] = vb.x; h_b[1] = vb.y; h_b[2] = vb.z; h_b[3] = vb.w;
    }
    c_a = c0g[(la * BB + batch) * 4 + j];
    c_b = c0g[(lb * BB + batch) * 4 + j];

    float* __restrict__ ys  = out;
    float* __restrict__ hso = out + (size_t)TT * BB * 4;
    float* __restrict__ cso = hso + (size_t)LL * BB * 4;

    const float* xb = x + batch * 2;
    float2 xa = *reinterpret_cast<const float2*>(xb);                  // x[0]
    float2 xn = *reinterpret_cast<const float2*>(xb + (size_t)BB * 2); // x[1]

    // initial hin: half0 = (x0[0], x0[1], -, -); half1 = h0 of layer 1
    {
        float t0 = __shfl_sync(0xffffffffu, h_b[0], 0, 32);
        float t1 = __shfl_sync(0xffffffffu, h_b[1], 1, 32);
        float t2 = __shfl_sync(0xffffffffu, h_b[2], 2, 32);
        float t3 = __shfl_sync(0xffffffffu, h_b[3], 3, 32);
        hin[0] = half ? t0 : xa.x;
        hin[1] = half ? t1 : xa.y;
        hin[2] = t2; hin[3] = t3;
    }

    // one layer update: activation, gate gather, cell, tanh, hidden broadcast
    auto update = [&](float z, float cc_old, float& cc_new,
                      float& h0o, float& h1o, float& h2o, float& h3o) {
        float a    = rcpf(1.0f + ex2f(z * s1));
        float gate = fmaf(a, m2, a2);
        float iv = __shfl_sync(0xffffffffu, gate, j,      16);
        float fv = __shfl_sync(0xffffffffu, gate, j + 4,  16);
        float gv = __shfl_sync(0xffffffffu, gate, j + 8,  16);
        float ov = __shfl_sync(0xffffffffu, gate, j + 12, 16);
        cc_new = fmaf(fv, cc_old, iv * gv);
        float r  = rcpf(1.0f + ex2f(cc_new * -2.8853900817779268f));
        float th = fmaf(r, 2.0f, -1.0f);
        float ho = ov * th;
        h0o = __shfl_sync(0xffffffffu, ho, 0, 16);
        h1o = __shfl_sync(0xffffffffu, ho, 1, 16);
        h2o = __shfl_sync(0xffffffffu, ho, 2, 16);
        h3o = __shfl_sync(0xffffffffu, ho, 3, 16);
    };

    auto body = [&](int s, bool masked) {
        // prefetch x two bodies ahead
        int tp = s + 2; if (tp > TT - 1) tp = TT - 1;
        float2 xf = *reinterpret_cast<const float2*>(xb + (size_t)tp * BB * 2);

        // active windows: layer l live for s in [l, l+TT-1]
        bool Aa = true, Ab = true;
        if (masked) {
            Aa = ((unsigned)(s - la) < (unsigned)TT);
            Ab = ((unsigned)(s - lb) < (unsigned)TT);
        }

        // pre-activations from OLD state
        float z_a = bz_a, z_b = bz_b;
#pragma unroll
        for (int k = 0; k < 4; k++) z_a = fmaf(win_a[k], hin[k], z_a);
#pragma unroll
        for (int k = 0; k < 4; k++) z_a = fmaf(wh_a[k], h_a[k], z_a);
#pragma unroll
        for (int k = 0; k < 4; k++) z_b = fmaf(win_b[k], h_a[k], z_b);
#pragma unroll
        for (int k = 0; k < 4; k++) z_b = fmaf(wh_b[k], h_b[k], z_b);

        // two independent layer updates
        float cna, na0, na1, na2, na3;
        update(z_a, c_a, cna, na0, na1, na2, na3);
        float cnb, nb0, nb1, nb2, nb3;
        update(z_b, c_b, cnb, nb0, nb1, nb2, nb3);

        if (Aa) {
            c_a = cna; h_a[0] = na0; h_a[1] = na1; h_a[2] = na2; h_a[3] = na3;
        }
        if (Ab) {
            c_b = cnb; h_b[0] = nb0; h_b[1] = nb1; h_b[2] = nb2; h_b[3] = nb3;
            if (half == 1 && g == 0) {   // layer 3 output row s-3
                *reinterpret_cast<float4*>(ys + ((size_t)(s - 3) * BB + batch) * 4) =
                    make_float4(h_b[0], h_b[1], h_b[2], h_b[3]);
            }
        }

        // cross-half handoff: h[1] (half0's h_b) -> hin of half1 for next body
        float t0 = __shfl_sync(0xffffffffu, h_b[0], 0, 32);
        float t1 = __shfl_sync(0xffffffffu, h_b[1], 1, 32);
        float t2 = __shfl_sync(0xffffffffu, h_b[2], 2, 32);
        float t3 = __shfl_sync(0xffffffffu, h_b[3], 3, 32);

        xa = xn; xn = xf;
        hin[0] = half ? t0 : xa.x;
        hin[1] = half ? t1 : xa.y;
        hin[2] = t2; hin[3] = t3;
    };

    body(0, true); body(1, true); body(2, true);
#pragma unroll 1
    for (int s = 3; s < TT; s++) body(s, false);
    body(TT, true); body(TT + 1, true); body(TT + 2, true);

    // ---- final hT / cT ----
    if (g == 0) {   // lanes 0 and 16
        *reinterpret_cast<float4*>(hso + (la * BB + batch) * 4) =
            make_float4(h_a[0], h_a[1], h_a[2], h_a[3]);
        *reinterpret_cast<float4*>(hso + (lb * BB + batch) * 4) =
            make_float4(h_b[0], h_b[1], h_b[2], h_b[3]);
    }
    if (gt == 0) {  // lanes 0-3 and 16-19
        cso[(la * BB + batch) * 4 + j] = c_a;
        cso[(lb * BB + batch) * 4 + j] = c_b;
    }
}

extern "C" void kernel_launch(void* const* d_in, const int* in_sizes, int n_in,
                              void* d_out, int out_size) {
    (void)in_sizes; (void)n_in; (void)out_size;
    const float* x    = (const float*)d_in[0];
    const float* h0   = (const float*)d_in[1];
    const float* c0   = (const float*)d_in[2];
    const float* Wih0 = (const float*)d_in[3];
    const float* Wr   = (const float*)d_in[4];
    const float* Whh  = (const float*)d_in[5];
    const float* bih  = (const float*)d_in[6];
    const float* bhh  = (const float*)d_in[7];
    // one warp per batch element: 2048 warps, 4 warps/block -> 512 blocks
    lstm_kernel<<<BB / 4, 128>>>(x, h0, c0, Wih0, Wr, Whh, bih, bhh, (float*)d_out);
}